// round 12
// baseline (speedup 1.0000x reference)
#include <cuda_runtime.h>
#include <cuda_bf16.h>
#include <math.h>
#include <stdint.h>

#define B 4096
#define T 48
#define F 35
#define H 1024
#define KP 1152            // 1024 h + 70 xcat + pad; 18 chunks of 64
#define NG 4096            // 4*H gate columns, n' = hid*4 + gate
#define BK 64
#define NCH (KP/BK)        // 18

typedef __nv_bfloat16 bf16;

// ---------------- scratch ----------------
__device__ bf16  g_A0[(size_t)B * KP];
__device__ bf16  g_A1[(size_t)B * KP];
__device__ bf16  g_Wp[(size_t)NG * KP];    // [n'][k]
__device__ float g_biasP[NG];
__device__ float g_tdWt[F * H];            // [f][hid]
__device__ float g_cp[(size_t)B * H];      // cell state, fragment-permuted
__device__ float g_xhp[(size_t)32 * F * B];// x_h partials [bn][f][b]
__device__ float g_num[T];
__device__ float g_msum[T];
__device__ float g_ynum, g_yden;

// ---------------- helpers ----------------
__device__ __forceinline__ uint32_t smem_u32(const void* p) {
    uint32_t a;
    asm("{ .reg .u64 t; cvta.to.shared.u64 t, %1; cvt.u32.u64 %0, t; }" : "=r"(a) : "l"(p));
    return a;
}
#define SW128(o) ((o) ^ (((o) >> 3) & 0x70))
#define CP_ASYNC16(dst, src) \
    asm volatile("cp.async.cg.shared.global [%0], [%1], 16;" :: "r"(dst), "l"(src))
#define CP_COMMIT() asm volatile("cp.async.commit_group;" ::: "memory")

__device__ __forceinline__ void ldsm_x4(uint32_t* r, uint32_t addr) {
    asm volatile("ldmatrix.sync.aligned.m8n8.x4.shared.b16 {%0,%1,%2,%3}, [%4];"
        : "=r"(r[0]), "=r"(r[1]), "=r"(r[2]), "=r"(r[3]) : "r"(addr));
}
__device__ __forceinline__ void mma_bf16(float* d, const uint32_t* a, const uint32_t* b) {
    asm volatile("mma.sync.aligned.m16n8k16.row.col.f32.bf16.bf16.f32 "
        "{%0,%1,%2,%3}, {%4,%5,%6,%7}, {%8,%9}, {%0,%1,%2,%3};"
        : "+f"(d[0]), "+f"(d[1]), "+f"(d[2]), "+f"(d[3])
        : "r"(a[0]), "r"(a[1]), "r"(a[2]), "r"(a[3]), "r"(b[0]), "r"(b[1]));
}
__device__ __forceinline__ float tanhap(float x) {
    float y;
    asm("tanh.approx.f32 %0, %1;" : "=f"(y) : "f"(x));
    return y;
}
__device__ __forceinline__ float sigm(float x) {       // 1 MUFU + 1 FMA
    return fmaf(0.5f, tanhap(0.5f * x), 0.5f);
}
__device__ __forceinline__ float tanh_acc(float x) {   // 1 MUFU
    return tanhap(x);
}

// ---------------- init / packing ----------------
__global__ void zero_state_a() {
    size_t i = (size_t)blockIdx.x * blockDim.x + threadIdx.x;
    size_t stride = (size_t)gridDim.x * blockDim.x;
    uint32_t* a0 = (uint32_t*)g_A0;
    uint32_t* a1 = (uint32_t*)g_A1;
    for (size_t idx = i; idx < (size_t)B * KP / 2; idx += stride) { a0[idx] = 0u; a1[idx] = 0u; }
    for (size_t idx = i; idx < (size_t)32 * F * B; idx += stride) g_xhp[idx] = 0.f;
}
__global__ void zero_state_b() {
    size_t i = (size_t)blockIdx.x * blockDim.x + threadIdx.x;
    size_t stride = (size_t)gridDim.x * blockDim.x;
    for (size_t idx = i; idx < (size_t)B * H; idx += stride) g_cp[idx] = 0.f;
    if (i < T) { g_num[i] = 0.f; g_msum[i] = 0.f; }
    if (i == 0) { g_ynum = 0.f; g_yden = 0.f; }
}

__global__ void pack_w_kernel(const float* __restrict__ W_hh, const float* __restrict__ W_ih) {
    size_t i = (size_t)blockIdx.x * blockDim.x + threadIdx.x;
    size_t stride = (size_t)gridDim.x * blockDim.x;
    for (size_t idx = i; idx < (size_t)NG * KP; idx += stride) {
        int np = (int)(idx / KP);
        int k  = (int)(idx - (size_t)np * KP);
        int n  = ((np & 3) << 10) + (np >> 2);
        float v = 0.f;
        if (k < H)              v = W_hh[(size_t)n * H + k];
        else if (k < H + 2 * F) v = W_ih[(size_t)n * (2 * F) + (k - H)];
        g_Wp[idx] = __float2bfloat16(v);
    }
}

__global__ void pack_misc_kernel(const float* __restrict__ td_W,
                                 const float* __restrict__ b_ih,
                                 const float* __restrict__ b_hh) {
    int idx = blockIdx.x * blockDim.x + threadIdx.x;
    if (idx < F * H) {
        int f = idx >> 10, hid = idx & 1023;
        g_tdWt[idx] = td_W[hid * F + f];
    } else if (idx < F * H + NG) {
        int np = idx - F * H;
        int n = ((np & 3) << 10) + (np >> 2);
        g_biasP[np] = b_ih[n] + b_hh[n];
    }
}

// ---------------- per-step: fuse partials -> x_c / imputation / losses / xcat ----------------
// 16 blocks x 256 threads, one thread per batch row.
__global__ void __launch_bounds__(256) fuse_kernel(
        const float* __restrict__ values, const float* __restrict__ masks,
        const float* __restrict__ reg_b, float* __restrict__ imp, int t, int par) {
    int b = blockIdx.x * 256 + threadIdx.x;
    bf16* Ab = par ? g_A1 : g_A0;

    float xh[F];
    #pragma unroll
    for (int f = 0; f < F; f++) xh[f] = reg_b[f];
    #pragma unroll 1
    for (int s = 0; s < 32; s++) {
        const float* src = g_xhp + (size_t)s * F * B + b;
        #pragma unroll
        for (int f = 0; f < F; f++) xh[f] += src[(size_t)f * B];
    }

    float xcv[F], mv[F];
    float ln = 0.f, lm = 0.f;
    const float* vrow = values + ((size_t)b * T + t) * F;
    const float* mrow = masks  + ((size_t)b * T + t) * F;
    float* irow = imp + ((size_t)b * T + t) * F;
    #pragma unroll
    for (int f = 0; f < F; f++) {
        float x = vrow[f], m = mrow[f];
        float xc = m * x + (1.f - m) * xh[f];
        irow[f] = xc;
        xcv[f] = xc; mv[f] = m;
        ln += fabsf(x - xh[f]) * m;
        lm += m;
    }

    // write xcat: 70 contiguous bf16 at A[b][H..H+70)
    uint32_t* dst = (uint32_t*)(Ab + (size_t)b * KP + H);
    #pragma unroll
    for (int j = 0; j < 35; j++) {
        int e0 = 2 * j, e1 = 2 * j + 1;
        float lo = (e0 < 35) ? xcv[e0] : mv[e0 - 35];
        float hi = (e1 < 35) ? xcv[e1] : mv[e1 - 35];
        __nv_bfloat162 p = __floats2bfloat162_rn(lo, hi);
        dst[j] = *(uint32_t*)&p;
    }

    // block reduce losses
    int lane = threadIdx.x & 31, w = threadIdx.x >> 5;
    __shared__ float rn[8], rm[8];
    #pragma unroll
    for (int o = 16; o > 0; o >>= 1) {
        ln += __shfl_down_sync(0xffffffffu, ln, o);
        lm += __shfl_down_sync(0xffffffffu, lm, o);
    }
    if (lane == 0) { rn[w] = ln; rm[w] = lm; }
    __syncthreads();
    if (threadIdx.x == 0) {
        float sn = 0.f, sm2 = 0.f;
        #pragma unroll
        for (int j = 0; j < 8; j++) { sn += rn[j]; sm2 += rm[j]; }
        atomicAdd(&g_num[t], sn);
        atomicAdd(&g_msum[t], sm2);
    }
}

// ---------------- per-step: bf16 mma GEMM (128x128) + fused LSTM + decay(t+1) + xh partial ----------------
// 256 threads, 8 warps (4m x 2n), warp tile 32x64. 2-stage cp.async.
__global__ void __launch_bounds__(256, 2) gemm_lstm_mma(
        const float* __restrict__ deltas, const float* __restrict__ td_b,
        const float* __restrict__ reg_W, int t, int par) {
    extern __shared__ char smraw[];
    uint32_t sb0 = smem_u32(smraw);
    uint32_t sb = (sb0 + 1023) & ~1023u;
    char* smb = smraw + (sb - sb0);

    const bf16* Ab = par ? g_A1 : g_A0;
    bf16* An = par ? g_A0 : g_A1;

    int tid = threadIdx.x;
    int bn = blockIdx.x * 128;
    int bm = blockIdx.y * 128;
    int lane = tid & 31, w = tid >> 5;
    int wm = w & 3, wn = w >> 2;

    const bf16* Ag = Ab   + (size_t)bm * KP;
    const bf16* Bg = g_Wp + (size_t)bn * KP;

    float d[2][8][4];
    #pragma unroll
    for (int mt = 0; mt < 2; mt++)
        #pragma unroll
        for (int nt = 0; nt < 8; nt++)
            #pragma unroll
            for (int q = 0; q < 4; q++) d[mt][nt][q] = 0.f;

    int arow  = (lane & 7) + ((lane >> 3) & 1) * 8;
    int acolh = lane >> 4;
    int brow  = (lane & 7) + (lane >> 4) * 8;
    int bcolh = (lane >> 3) & 1;
    uint32_t aoff[2], boff[4];
    #pragma unroll
    for (int mt = 0; mt < 2; mt++)
        aoff[mt] = (uint32_t)((wm * 32 + mt * 16 + arow) * 128 + acolh * 16);
    #pragma unroll
    for (int p = 0; p < 4; p++)
        boff[p] = (uint32_t)((wn * 64 + p * 16 + brow) * 128 + bcolh * 16);

    // stage s at sb + s*32768: A 16KB | B 16KB
    #pragma unroll 1
    for (int pre = 0; pre < 2; pre++) {
        uint32_t abase = sb + pre * 32768, bbase = abase + 16384;
        const bf16* Asrc = Ag + pre * BK;
        const bf16* Bsrc = Bg + pre * BK;
        #pragma unroll
        for (int it = 0; it < 4; it++) {
            int slot = it * 256 + tid;
            int row = slot >> 3, col = slot & 7;
            uint32_t off = (uint32_t)(row * 128 + col * 16);
            CP_ASYNC16(abase + SW128(off), Asrc + (size_t)row * KP + col * 8);
        }
        #pragma unroll
        for (int it = 0; it < 4; it++) {
            int slot = it * 256 + tid;
            int row = slot >> 3, col = slot & 7;
            uint32_t off = (uint32_t)(row * 128 + col * 16);
            CP_ASYNC16(bbase + SW128(off), Bsrc + (size_t)row * KP + col * 8);
        }
        CP_COMMIT();
    }

    for (int i = 0; i < NCH; i++) {
        if (i < NCH - 1) asm volatile("cp.async.wait_group 1;" ::: "memory");
        else             asm volatile("cp.async.wait_group 0;" ::: "memory");
        __syncthreads();
        uint32_t at = sb + (i & 1) * 32768;
        uint32_t bt = at + 16384;
        #pragma unroll
        for (int kk = 0; kk < 4; kk++) {
            uint32_t afr[2][4], bfr[8][2];
            #pragma unroll
            for (int mt = 0; mt < 2; mt++)
                ldsm_x4(afr[mt], at + SW128(aoff[mt] + kk * 32));
            #pragma unroll
            for (int p = 0; p < 4; p++) {
                uint32_t r[4];
                ldsm_x4(r, bt + SW128(boff[p] + kk * 32));
                bfr[2 * p][0] = r[0]; bfr[2 * p][1] = r[1];
                bfr[2 * p + 1][0] = r[2]; bfr[2 * p + 1][1] = r[3];
            }
            #pragma unroll
            for (int mt = 0; mt < 2; mt++)
                #pragma unroll
                for (int nt = 0; nt < 8; nt++)
                    mma_bf16(d[mt][nt], afr[mt], bfr[nt]);
        }
        __syncthreads();
        if (i + 2 < NCH) {
            uint32_t abase = sb + (i & 1) * 32768, bbase = abase + 16384;
            const bf16* Asrc = Ag + (size_t)(i + 2) * BK;
            const bf16* Bsrc = Bg + (size_t)(i + 2) * BK;
            #pragma unroll
            for (int it = 0; it < 4; it++) {
                int slot = it * 256 + tid;
                int row = slot >> 3, col = slot & 7;
                uint32_t off = (uint32_t)(row * 128 + col * 16);
                CP_ASYNC16(abase + SW128(off), Asrc + (size_t)row * KP + col * 8);
            }
            #pragma unroll
            for (int it = 0; it < 4; it++) {
                int slot = it * 256 + tid;
                int row = slot >> 3, col = slot & 7;
                uint32_t off = (uint32_t)(row * 128 + col * 16);
                CP_ASYNC16(bbase + SW128(off), Bsrc + (size_t)row * KP + col * 8);
            }
            CP_COMMIT();
        }
    }
    __syncthreads();   // pipeline smem dead; reuse for epilogue

    float* dsm  = (float*)smb;             // [128][36] deltas(t+1)      18432 B
    float* tdsm = (float*)(smb + 18432);   // [35][32] td_W slice         4480 B
    float* tdbs = (float*)(smb + 22912);   // [32] td_b slice              128 B
    bf16*  hst  = (bf16*)(smb + 23040);    // [32][136] raw h staging     8704 B
    float* rsm  = (float*)(smb + 31744);   // [35][32] reg_W slice        4480 B

    int t1 = t + 1;
    bool hasd = (t1 < T);
    if (hasd) {
        for (int idx = tid; idx < 128 * F; idx += 256) {
            int bl = idx / F, f = idx - bl * F;
            dsm[bl * 36 + f] = deltas[((size_t)(bm + bl) * T + t1) * F + f];
        }
        for (int idx = tid; idx < F * 32; idx += 256) {
            int f = idx >> 5, hl = idx & 31;
            tdsm[f * 32 + hl] = g_tdWt[f * H + (bn >> 2) + hl];
            rsm[f * 32 + hl]  = reg_W[(size_t)f * H + (bn >> 2) + hl];
        }
        if (tid < 32) tdbs[tid] = td_b[(bn >> 2) + tid];
    }

    // pass A: activations + cell update, stage raw h
    int gid = lane >> 2, tig = lane & 3;
    int lane_e = gid * 2 + (tig >> 1);
    size_t cbase = (size_t)(blockIdx.y * 32 + blockIdx.x) * 4096 + (size_t)w * 512;
    #pragma unroll
    for (int mt = 0; mt < 2; mt++) {
        #pragma unroll
        for (int nt = 0; nt < 8; nt++) {
            float* dd = d[mt][nt];
            float o0 = __shfl_xor_sync(0xffffffffu, dd[0], 1);
            float o1 = __shfl_xor_sync(0xffffffffu, dd[1], 1);
            float o2 = __shfl_xor_sync(0xffffffffu, dd[2], 1);
            float o3 = __shfl_xor_sync(0xffffffffu, dd[3], 1);
            if ((tig & 1) == 0) {
                int npb = bn + wn * 64 + nt * 8 + tig * 2;
                int hl  = wn * 16 + nt * 2 + (tig >> 1);
                float4 bias = *(const float4*)(g_biasP + npb);
                int bl0 = wm * 32 + mt * 16 + gid;
                size_t ci = cbase + (size_t)((mt * 8 + nt) * 2) * 16 + lane_e;
                {
                    float ig = sigm(dd[0] + bias.x);
                    float fg = sigm(dd[1] + bias.y);
                    float gg = tanh_acc(o0 + bias.z);
                    float og = sigm(o1 + bias.w);
                    float cc = fg * g_cp[ci] + ig * gg;
                    g_cp[ci] = cc;
                    hst[hl * 136 + bl0] = __float2bfloat16(og * tanh_acc(cc));
                }
                {
                    float ig = sigm(dd[2] + bias.x);
                    float fg = sigm(dd[3] + bias.y);
                    float gg = tanh_acc(o2 + bias.z);
                    float og = sigm(o3 + bias.w);
                    float cc = fg * g_cp[ci + 16] + ig * gg;
                    g_cp[ci + 16] = cc;
                    hst[hl * 136 + bl0 + 8] = __float2bfloat16(og * tanh_acc(cc));
                }
            }
        }
    }
    __syncthreads();

    // pass B: decay for step t+1, A_next h-part write, x_h partial for step t+1
    {
        int bl = tid >> 1, hg = tid & 1;
        float drow[F];
        if (hasd) {
            #pragma unroll
            for (int f = 0; f < F; f++) drow[f] = dsm[bl * 36 + f];
        }
        bf16 av[16];
        #pragma unroll
        for (int hh = 0; hh < 16; hh++) {
            int hl = hg * 16 + hh;
            float hv = __bfloat162float(hst[hl * 136 + bl]);
            float gam = 1.f;
            if (hasd) {
                float a = tdbs[hl];
                #pragma unroll
                for (int f = 0; f < F; f++) a = fmaf(drow[f], tdsm[f * 32 + hl], a);
                gam = __expf(-fmaxf(a, 0.f));
            }
            av[hh] = __float2bfloat16(hv * gam);
        }
        bf16* dst = An + (size_t)(bm + bl) * KP + (bn >> 2) + hg * 16;
        *(uint4*)dst       = *(uint4*)&av[0];
        *(uint4*)(dst + 8) = *(uint4*)&av[8];

        // x_h partials: 32-hid slice dot reg_W, pair-reduced across hg.
        // No avf[] array: convert av (bf16, already live) inline -> no register spill.
        if (hasd) {
            const float* __restrict__ rbase = rsm + hg * 16;
            #pragma unroll 1
            for (int f = 0; f < F; f++) {
                float s = 0.f;
                #pragma unroll
                for (int hh = 0; hh < 16; hh++)
                    s = fmaf(__bfloat162float(av[hh]), rbase[f * 32 + hh], s);
                s += __shfl_xor_sync(0xffffffffu, s, 1);
                if (hg == 0)
                    g_xhp[((size_t)blockIdx.x * F + f) * B + (bm + bl)] = s;
            }
        }
    }
}

// ---------------- final head ----------------
__global__ void y_kernel(const float* __restrict__ labels, const float* __restrict__ is_train,
                         const float* __restrict__ out_W, const float* __restrict__ out_b,
                         float* __restrict__ pred) {
    int warp = threadIdx.x >> 5, lane = threadIdx.x & 31;
    int b = blockIdx.x * 8 + warp;
    const uint32_t* hp = (const uint32_t*)(g_A0 + (size_t)b * KP);   // raw h after step 47
    float s = 0.f;
    #pragma unroll
    for (int j = 0; j < 16; j++) {
        uint32_t hu = hp[j * 32 + lane];
        float2 hf = __bfloat1622float2(*reinterpret_cast<const __nv_bfloat162*>(&hu));
        float2 wf = *(const float2*)(out_W + (j * 32 + lane) * 2);
        s = fmaf(hf.x, wf.x, s);
        s = fmaf(hf.y, wf.y, s);
    }
    #pragma unroll
    for (int o = 16; o > 0; o >>= 1) s += __shfl_down_sync(0xffffffffu, s, o);
    if (lane == 0) {
        float y = s + out_b[0];
        pred[b] = 1.f / (1.f + expf(-y));
        float lab = labels[b], tr = is_train[b];
        float mv = fmaxf(-y, 0.f);
        float bce = y - y * lab + mv + logf(expf(-mv) + expf(-y - mv));
        atomicAdd(&g_ynum, bce * tr);
        atomicAdd(&g_yden, tr);
    }
}

__global__ void fin_kernel(float* __restrict__ out) {
    __shared__ float sh[T];
    if (threadIdx.x < T)
        sh[threadIdx.x] = g_num[threadIdx.x] / (g_msum[threadIdx.x] + 1e-5f);
    __syncthreads();
    if (threadIdx.x == 0) {
        float s = 0.f;
        for (int t = 0; t < T; t++) s += sh[t];
        out[0] = 0.3f * s + g_ynum / (g_yden + 1e-5f);
    }
}

// ---------------- launch ----------------
extern "C" void kernel_launch(void* const* d_in, const int* in_sizes, int n_in,
                              void* d_out, int out_size) {
    const float* values   = (const float*)d_in[0];
    const float* masks    = (const float*)d_in[1];
    const float* deltas   = (const float*)d_in[2];
    const float* labels   = (const float*)d_in[3];
    const float* is_train = (const float*)d_in[4];
    const float* td_W     = (const float*)d_in[5];
    const float* td_b     = (const float*)d_in[6];
    const float* W_ih     = (const float*)d_in[7];
    const float* W_hh     = (const float*)d_in[8];
    const float* b_ih     = (const float*)d_in[9];
    const float* b_hh     = (const float*)d_in[10];
    const float* reg_W    = (const float*)d_in[11];
    const float* reg_b    = (const float*)d_in[12];
    const float* out_W    = (const float*)d_in[13];
    const float* out_b    = (const float*)d_in[14];

    float* out  = (float*)d_out;
    float* pred = out + 1;
    float* imp  = out + 1 + B;

    cudaFuncSetAttribute(gemm_lstm_mma, cudaFuncAttributeMaxDynamicSharedMemorySize, 66560);

    zero_state_a<<<2048, 256>>>();
    zero_state_b<<<2048, 256>>>();
    pack_w_kernel<<<4096, 256>>>(W_hh, W_ih);
    pack_misc_kernel<<<(F * H + NG + 255) / 256, 256>>>(td_W, b_ih, b_hh);

    for (int t = 0; t < T; t++) {
        fuse_kernel<<<16, 256>>>(values, masks, reg_b, imp, t, t & 1);
        gemm_lstm_mma<<<dim3(32, 32), 256, 66560>>>(deltas, td_b, reg_W, t, t & 1);
    }

    y_kernel<<<512, 256>>>(labels, is_train, out_W, out_b, pred);
    fin_kernel<<<1, 64>>>(out);
}

// round 13
// speedup vs baseline: 1.3705x; 1.3705x over previous
#include <cuda_runtime.h>
#include <cuda_bf16.h>
#include <math.h>
#include <stdint.h>

#define B 4096
#define T 48
#define F 35
#define H 1024
#define KP 1152            // 1024 h + 70 xcat + pad; 18 chunks of 64
#define NG 4096            // 4*H gate columns, n' = hid*4 + gate
#define BK 64
#define NCH (KP/BK)        // 18

typedef __nv_bfloat16 bf16;

// ---------------- scratch ----------------
__device__ bf16  g_A0[(size_t)B * KP];
__device__ bf16  g_A1[(size_t)B * KP];
__device__ bf16  g_Wp[(size_t)NG * KP];    // [n'][k]
__device__ bf16  g_Rp[(size_t)64 * H];     // reg_W padded [48->64][1024]
__device__ float g_biasP[NG];
__device__ float g_tdWt[F * H];            // [f][hid]
__device__ float g_cp[(size_t)B * H];      // cell state, fragment-permuted
__device__ int   g_flag[T];                // xcat-ready flags
__device__ float g_num[T];
__device__ float g_msum[T];
__device__ float g_ynum, g_yden;

// ---------------- helpers ----------------
__device__ __forceinline__ uint32_t smem_u32(const void* p) {
    uint32_t a;
    asm("{ .reg .u64 t; cvta.to.shared.u64 t, %1; cvt.u32.u64 %0, t; }" : "=r"(a) : "l"(p));
    return a;
}
#define SW128(o) ((o) ^ (((o) >> 3) & 0x70))
#define CP_ASYNC16(dst, src) \
    asm volatile("cp.async.cg.shared.global [%0], [%1], 16;" :: "r"(dst), "l"(src))
#define CP_COMMIT() asm volatile("cp.async.commit_group;" ::: "memory")

__device__ __forceinline__ void ldsm_x4(uint32_t* r, uint32_t addr) {
    asm volatile("ldmatrix.sync.aligned.m8n8.x4.shared.b16 {%0,%1,%2,%3}, [%4];"
        : "=r"(r[0]), "=r"(r[1]), "=r"(r[2]), "=r"(r[3]) : "r"(addr));
}
__device__ __forceinline__ void mma_bf16(float* d, const uint32_t* a, const uint32_t* b) {
    asm volatile("mma.sync.aligned.m16n8k16.row.col.f32.bf16.bf16.f32 "
        "{%0,%1,%2,%3}, {%4,%5,%6,%7}, {%8,%9}, {%0,%1,%2,%3};"
        : "+f"(d[0]), "+f"(d[1]), "+f"(d[2]), "+f"(d[3])
        : "r"(a[0]), "r"(a[1]), "r"(a[2]), "r"(a[3]), "r"(b[0]), "r"(b[1]));
}
__device__ __forceinline__ float tanhap(float x) {
    float y;
    asm("tanh.approx.f32 %0, %1;" : "=f"(y) : "f"(x));
    return y;
}
__device__ __forceinline__ float sigm(float x) {       // 1 MUFU + 1 FMA
    return fmaf(0.5f, tanhap(0.5f * x), 0.5f);
}
__device__ __forceinline__ float tanh_acc(float x) {   // 1 MUFU
    return tanhap(x);
}

// ---------------- init / packing ----------------
__global__ void zero_state_a() {
    size_t i = (size_t)blockIdx.x * blockDim.x + threadIdx.x;
    size_t stride = (size_t)gridDim.x * blockDim.x;
    uint32_t* a0 = (uint32_t*)g_A0;
    uint32_t* a1 = (uint32_t*)g_A1;
    for (size_t idx = i; idx < (size_t)B * KP / 2; idx += stride) { a0[idx] = 0u; a1[idx] = 0u; }
}
__global__ void zero_state_b() {
    size_t i = (size_t)blockIdx.x * blockDim.x + threadIdx.x;
    size_t stride = (size_t)gridDim.x * blockDim.x;
    for (size_t idx = i; idx < (size_t)B * H; idx += stride) g_cp[idx] = 0.f;
    if (i < T) { g_num[i] = 0.f; g_msum[i] = 0.f; g_flag[i] = 0; }
    if (i == 0) { g_ynum = 0.f; g_yden = 0.f; }
}

__global__ void pack_w_kernel(const float* __restrict__ W_hh, const float* __restrict__ W_ih) {
    size_t i = (size_t)blockIdx.x * blockDim.x + threadIdx.x;
    size_t stride = (size_t)gridDim.x * blockDim.x;
    for (size_t idx = i; idx < (size_t)NG * KP; idx += stride) {
        int np = (int)(idx / KP);
        int k  = (int)(idx - (size_t)np * KP);
        int n  = ((np & 3) << 10) + (np >> 2);
        float v = 0.f;
        if (k < H)              v = W_hh[(size_t)n * H + k];
        else if (k < H + 2 * F) v = W_ih[(size_t)n * (2 * F) + (k - H)];
        g_Wp[idx] = __float2bfloat16(v);
    }
}

__global__ void pack_misc_kernel(const float* __restrict__ td_W,
                                 const float* __restrict__ b_ih,
                                 const float* __restrict__ b_hh,
                                 const float* __restrict__ reg_W) {
    int idx = blockIdx.x * blockDim.x + threadIdx.x;
    if (idx < F * H) {
        int f = idx >> 10, hid = idx & 1023;
        g_tdWt[idx] = td_W[hid * F + f];
    } else if (idx < F * H + NG) {
        int np = idx - F * H;
        int n = ((np & 3) << 10) + (np >> 2);
        g_biasP[np] = b_ih[n] + b_hh[n];
    } else if (idx < F * H + NG + 64 * H) {
        int j = idx - (F * H + NG);
        int n = j >> 10, k = j & 1023;
        g_Rp[j] = (n < F) ? __float2bfloat16(reg_W[n * H + k]) : __float2bfloat16(0.f);
    }
}

// ---------------- fused per-step kernel ----------------
// grid 1056: blocks 0..31 = reg GEMM (BM=128, N=64, K=1024, 2-stage);
//            blocks 32..1055 = gate GEMM 128x128 + LSTM + decay(t+1).
// Gate blocks spin on g_flag[t]==32 before prefetching k-chunk 16 (xcat cols).
__global__ void __launch_bounds__(256, 2) step_kernel(
        const float* __restrict__ values, const float* __restrict__ masks,
        const float* __restrict__ reg_b, float* __restrict__ imp,
        const float* __restrict__ deltas, const float* __restrict__ td_b,
        int t, int par) {
    extern __shared__ char smraw[];
    uint32_t sb0 = smem_u32(smraw);
    uint32_t sb = (sb0 + 1023) & ~1023u;
    char* smb = smraw + (sb - sb0);
    int tid = threadIdx.x;
    int lane = tid & 31, w = tid >> 5;

    if (blockIdx.x < 32) {
        // ================= REG branch =================
        bf16* Ab = par ? g_A1 : g_A0;
        int bm = blockIdx.x * 128;
        int wm = w & 3, wn = w >> 2;

        float d[2][4][4];
        #pragma unroll
        for (int mt = 0; mt < 2; mt++)
            #pragma unroll
            for (int nt = 0; nt < 4; nt++)
                #pragma unroll
                for (int q = 0; q < 4; q++) d[mt][nt][q] = 0.f;

        int arow  = (lane & 7) + ((lane >> 3) & 1) * 8;
        int acolh = lane >> 4;
        int brow  = (lane & 7) + (lane >> 4) * 8;
        int bcolh = (lane >> 3) & 1;
        uint32_t aoff[2], boff[2];
        #pragma unroll
        for (int mt = 0; mt < 2; mt++)
            aoff[mt] = (uint32_t)((wm * 32 + mt * 16 + arow) * 128 + acolh * 16);
        #pragma unroll
        for (int p = 0; p < 2; p++)
            boff[p] = (uint32_t)((wn * 32 + p * 16 + brow) * 128 + bcolh * 16);

        #pragma unroll 1
        for (int pre = 0; pre < 2; pre++) {
            uint32_t abase = sb + pre * 24576, bbase = abase + 16384;
            int k0 = pre * BK;
            #pragma unroll
            for (int it = 0; it < 4; it++) {
                int slot = it * 256 + tid;
                int row = slot >> 3, col = slot & 7;
                uint32_t off = (uint32_t)(row * 128 + col * 16);
                CP_ASYNC16(abase + SW128(off), Ab + (size_t)(bm + row) * KP + k0 + col * 8);
            }
            #pragma unroll
            for (int it = 0; it < 2; it++) {
                int slot = it * 256 + tid;
                int row = slot >> 3, col = slot & 7;
                uint32_t off = (uint32_t)(row * 128 + col * 16);
                CP_ASYNC16(bbase + SW128(off), g_Rp + (size_t)row * H + k0 + col * 8);
            }
            CP_COMMIT();
        }

        for (int i = 0; i < 16; i++) {
            if (i < 15) asm volatile("cp.async.wait_group 1;" ::: "memory");
            else        asm volatile("cp.async.wait_group 0;" ::: "memory");
            __syncthreads();
            uint32_t at = sb + (i & 1) * 24576;
            uint32_t bt = at + 16384;
            #pragma unroll
            for (int kk = 0; kk < 4; kk++) {
                uint32_t afr[2][4], bfr[4][2];
                #pragma unroll
                for (int mt = 0; mt < 2; mt++)
                    ldsm_x4(afr[mt], at + SW128(aoff[mt] + kk * 32));
                #pragma unroll
                for (int p = 0; p < 2; p++) {
                    uint32_t r[4];
                    ldsm_x4(r, bt + SW128(boff[p] + kk * 32));
                    bfr[2 * p][0] = r[0]; bfr[2 * p][1] = r[1];
                    bfr[2 * p + 1][0] = r[2]; bfr[2 * p + 1][1] = r[3];
                }
                #pragma unroll
                for (int mt = 0; mt < 2; mt++)
                    #pragma unroll
                    for (int nt = 0; nt < 4; nt++)
                        mma_bf16(d[mt][nt], afr[mt], bfr[nt]);
            }
            __syncthreads();
            if (i + 2 < 16) {
                uint32_t abase = sb + (i & 1) * 24576, bbase = abase + 16384;
                int k0 = (i + 2) * BK;
                #pragma unroll
                for (int it = 0; it < 4; it++) {
                    int slot = it * 256 + tid;
                    int row = slot >> 3, col = slot & 7;
                    uint32_t off = (uint32_t)(row * 128 + col * 16);
                    CP_ASYNC16(abase + SW128(off), Ab + (size_t)(bm + row) * KP + k0 + col * 8);
                }
                #pragma unroll
                for (int it = 0; it < 2; it++) {
                    int slot = it * 256 + tid;
                    int row = slot >> 3, col = slot & 7;
                    uint32_t off = (uint32_t)(row * 128 + col * 16);
                    CP_ASYNC16(bbase + SW128(off), g_Rp + (size_t)row * H + k0 + col * 8);
                }
                CP_COMMIT();
            }
        }
        __syncthreads();

        float* xsm  = (float*)smb;
        bf16*  xcsm = (bf16*)(smb + 128 * 66 * 4);
        __shared__ float rn[8], rm[8];

        int gid = lane >> 2, tig = lane & 3;
        #pragma unroll
        for (int mt = 0; mt < 2; mt++) {
            #pragma unroll
            for (int nt = 0; nt < 4; nt++) {
                int r0 = wm * 32 + mt * 16 + gid;
                int c  = wn * 32 + nt * 8 + tig * 2;
                xsm[r0 * 66 + c]           = d[mt][nt][0];
                xsm[r0 * 66 + c + 1]       = d[mt][nt][1];
                xsm[(r0 + 8) * 66 + c]     = d[mt][nt][2];
                xsm[(r0 + 8) * 66 + c + 1] = d[mt][nt][3];
            }
        }
        __syncthreads();

        int row = tid >> 1, half = tid & 1;
        int f0 = half ? 18 : 0, f1 = half ? 35 : 18;
        int b = bm + row;
        float ln = 0.f, lm = 0.f;
        for (int f = f0; f < f1; f++) {
            float xh = xsm[row * 66 + f] + reg_b[f];
            size_t gi = ((size_t)b * T + t) * F + f;
            float x = values[gi], m = masks[gi];
            float xc = m * x + (1.f - m) * xh;
            imp[gi] = xc;
            xcsm[row * 72 + f]      = __float2bfloat16(xc);
            xcsm[row * 72 + 35 + f] = __float2bfloat16(m);
            ln += fabsf(x - xh) * m;
            lm += m;
        }
        if (half) { xcsm[row * 72 + 70] = __float2bfloat16(0.f); xcsm[row * 72 + 71] = __float2bfloat16(0.f); }
        __syncthreads();

        const uint32_t* xcu = (const uint32_t*)xcsm;
        #pragma unroll
        for (int j = 0; j < 18; j++) {
            int idx = j * 256 + tid;
            int r = idx / 36, q = idx - r * 36;
            *(uint32_t*)(Ab + (size_t)(bm + r) * KP + H + q * 2) = xcu[r * 36 + q];
        }

        // publish xcat for this bm block, then reduce losses
        __threadfence();
        __syncthreads();
        if (tid == 0) atomicAdd(&g_flag[t], 1);

        #pragma unroll
        for (int o = 16; o > 0; o >>= 1) {
            ln += __shfl_down_sync(0xffffffffu, ln, o);
            lm += __shfl_down_sync(0xffffffffu, lm, o);
        }
        if (lane == 0) { rn[w] = ln; rm[w] = lm; }
        __syncthreads();
        if (tid == 0) {
            float sn = 0.f, sm2 = 0.f;
            #pragma unroll
            for (int j = 0; j < 8; j++) { sn += rn[j]; sm2 += rm[j]; }
            atomicAdd(&g_num[t], sn);
            atomicAdd(&g_msum[t], sm2);
        }
        return;
    }

    // ================= GATE branch =================
    {
        const bf16* Ab = par ? g_A1 : g_A0;
        bf16* An = par ? g_A0 : g_A1;

        int gidb = blockIdx.x - 32;
        int bxn = gidb & 31, byn = gidb >> 5;
        int bn = bxn * 128;
        int bm = byn * 128;
        int wm = w & 3, wn = w >> 2;

        const bf16* Ag = Ab   + (size_t)bm * KP;
        const bf16* Bg = g_Wp + (size_t)bn * KP;

        float d[2][8][4];
        #pragma unroll
        for (int mt = 0; mt < 2; mt++)
            #pragma unroll
            for (int nt = 0; nt < 8; nt++)
                #pragma unroll
                for (int q = 0; q < 4; q++) d[mt][nt][q] = 0.f;

        int arow  = (lane & 7) + ((lane >> 3) & 1) * 8;
        int acolh = lane >> 4;
        int brow  = (lane & 7) + (lane >> 4) * 8;
        int bcolh = (lane >> 3) & 1;
        uint32_t aoff[2], boff[4];
        #pragma unroll
        for (int mt = 0; mt < 2; mt++)
            aoff[mt] = (uint32_t)((wm * 32 + mt * 16 + arow) * 128 + acolh * 16);
        #pragma unroll
        for (int p = 0; p < 4; p++)
            boff[p] = (uint32_t)((wn * 64 + p * 16 + brow) * 128 + bcolh * 16);

        #pragma unroll 1
        for (int pre = 0; pre < 2; pre++) {
            uint32_t abase = sb + pre * 32768, bbase = abase + 16384;
            const bf16* Asrc = Ag + pre * BK;
            const bf16* Bsrc = Bg + pre * BK;
            #pragma unroll
            for (int it = 0; it < 4; it++) {
                int slot = it * 256 + tid;
                int row = slot >> 3, col = slot & 7;
                uint32_t off = (uint32_t)(row * 128 + col * 16);
                CP_ASYNC16(abase + SW128(off), Asrc + (size_t)row * KP + col * 8);
            }
            #pragma unroll
            for (int it = 0; it < 4; it++) {
                int slot = it * 256 + tid;
                int row = slot >> 3, col = slot & 7;
                uint32_t off = (uint32_t)(row * 128 + col * 16);
                CP_ASYNC16(bbase + SW128(off), Bsrc + (size_t)row * KP + col * 8);
            }
            CP_COMMIT();
        }

        for (int i = 0; i < NCH; i++) {
            if (i < NCH - 1) asm volatile("cp.async.wait_group 1;" ::: "memory");
            else             asm volatile("cp.async.wait_group 0;" ::: "memory");
            __syncthreads();
            uint32_t at = sb + (i & 1) * 32768;
            uint32_t bt = at + 16384;
            #pragma unroll
            for (int kk = 0; kk < 4; kk++) {
                uint32_t afr[2][4], bfr[8][2];
                #pragma unroll
                for (int mt = 0; mt < 2; mt++)
                    ldsm_x4(afr[mt], at + SW128(aoff[mt] + kk * 32));
                #pragma unroll
                for (int p = 0; p < 4; p++) {
                    uint32_t r[4];
                    ldsm_x4(r, bt + SW128(boff[p] + kk * 32));
                    bfr[2 * p][0] = r[0]; bfr[2 * p][1] = r[1];
                    bfr[2 * p + 1][0] = r[2]; bfr[2 * p + 1][1] = r[3];
                }
                #pragma unroll
                for (int mt = 0; mt < 2; mt++)
                    #pragma unroll
                    for (int nt = 0; nt < 8; nt++)
                        mma_bf16(d[mt][nt], afr[mt], bfr[nt]);
            }
            __syncthreads();
            if (i + 2 < NCH) {
                if (i + 2 == 16) {   // chunk 16 holds xcat cols -> wait for reg blocks
                    if (tid == 0) {
                        while (*(volatile int*)&g_flag[t] < 32) { }
                    }
                    __syncthreads();
                }
                uint32_t abase = sb + (i & 1) * 32768, bbase = abase + 16384;
                const bf16* Asrc = Ag + (size_t)(i + 2) * BK;
                const bf16* Bsrc = Bg + (size_t)(i + 2) * BK;
                #pragma unroll
                for (int it = 0; it < 4; it++) {
                    int slot = it * 256 + tid;
                    int row = slot >> 3, col = slot & 7;
                    uint32_t off = (uint32_t)(row * 128 + col * 16);
                    CP_ASYNC16(abase + SW128(off), Asrc + (size_t)row * KP + col * 8);
                }
                #pragma unroll
                for (int it = 0; it < 4; it++) {
                    int slot = it * 256 + tid;
                    int row = slot >> 3, col = slot & 7;
                    uint32_t off = (uint32_t)(row * 128 + col * 16);
                    CP_ASYNC16(bbase + SW128(off), Bsrc + (size_t)row * KP + col * 8);
                }
                CP_COMMIT();
            }
        }
        __syncthreads();   // pipeline smem dead; reuse for epilogue

        float* dsm  = (float*)smb;             // [128][36]
        float* tdsm = (float*)(smb + 18432);   // [35][32]
        float* tdbs = (float*)(smb + 22912);   // [32]
        bf16*  hst  = (bf16*)(smb + 23040);    // [32][136]

        int t1 = t + 1;
        bool hasd = (t1 < T);
        if (hasd) {
            for (int idx = tid; idx < 128 * F; idx += 256) {
                int bl = idx / F, f = idx - bl * F;
                dsm[bl * 36 + f] = deltas[((size_t)(bm + bl) * T + t1) * F + f];
            }
            for (int idx = tid; idx < F * 32; idx += 256) {
                int f = idx >> 5, hl = idx & 31;
                tdsm[f * 32 + hl] = g_tdWt[f * H + (bn >> 2) + hl];
            }
            if (tid < 32) tdbs[tid] = td_b[(bn >> 2) + tid];
        }

        int gid = lane >> 2, tig = lane & 3;
        int lane_e = gid * 2 + (tig >> 1);
        size_t cbase = (size_t)gidb * 4096 + (size_t)w * 512;
        #pragma unroll
        for (int mt = 0; mt < 2; mt++) {
            #pragma unroll
            for (int nt = 0; nt < 8; nt++) {
                float* dd = d[mt][nt];
                float o0 = __shfl_xor_sync(0xffffffffu, dd[0], 1);
                float o1 = __shfl_xor_sync(0xffffffffu, dd[1], 1);
                float o2 = __shfl_xor_sync(0xffffffffu, dd[2], 1);
                float o3 = __shfl_xor_sync(0xffffffffu, dd[3], 1);
                if ((tig & 1) == 0) {
                    int npb = bn + wn * 64 + nt * 8 + tig * 2;
                    int hl  = wn * 16 + nt * 2 + (tig >> 1);
                    float4 bias = *(const float4*)(g_biasP + npb);
                    int bl0 = wm * 32 + mt * 16 + gid;
                    size_t ci = cbase + (size_t)((mt * 8 + nt) * 2) * 16 + lane_e;
                    {
                        float ig = sigm(dd[0] + bias.x);
                        float fg = sigm(dd[1] + bias.y);
                        float gg = tanh_acc(o0 + bias.z);
                        float og = sigm(o1 + bias.w);
                        float cc = fg * g_cp[ci] + ig * gg;
                        g_cp[ci] = cc;
                        hst[hl * 136 + bl0] = __float2bfloat16(og * tanh_acc(cc));
                    }
                    {
                        float ig = sigm(dd[2] + bias.x);
                        float fg = sigm(dd[3] + bias.y);
                        float gg = tanh_acc(o2 + bias.z);
                        float og = sigm(o3 + bias.w);
                        float cc = fg * g_cp[ci + 16] + ig * gg;
                        g_cp[ci + 16] = cc;
                        hst[hl * 136 + bl0 + 8] = __float2bfloat16(og * tanh_acc(cc));
                    }
                }
            }
        }
        __syncthreads();

        {
            int bl = tid >> 1, hg = tid & 1;
            float drow[F];
            if (hasd) {
                #pragma unroll
                for (int f = 0; f < F; f++) drow[f] = dsm[bl * 36 + f];
            }
            bf16 av[16];
            #pragma unroll
            for (int hh = 0; hh < 16; hh++) {
                int hl = hg * 16 + hh;
                float hv = __bfloat162float(hst[hl * 136 + bl]);
                float gam = 1.f;
                if (hasd) {
                    float a = tdbs[hl];
                    #pragma unroll
                    for (int f = 0; f < F; f++) a = fmaf(drow[f], tdsm[f * 32 + hl], a);
                    gam = __expf(-fmaxf(a, 0.f));
                }
                av[hh] = __float2bfloat16(hv * gam);
            }
            bf16* dst = An + (size_t)(bm + bl) * KP + (bn >> 2) + hg * 16;
            *(uint4*)dst       = *(uint4*)&av[0];
            *(uint4*)(dst + 8) = *(uint4*)&av[8];
        }
    }
}

// ---------------- final head ----------------
__global__ void y_kernel(const float* __restrict__ labels, const float* __restrict__ is_train,
                         const float* __restrict__ out_W, const float* __restrict__ out_b,
                         float* __restrict__ pred) {
    int warp = threadIdx.x >> 5, lane = threadIdx.x & 31;
    int b = blockIdx.x * 8 + warp;
    const uint32_t* hp = (const uint32_t*)(g_A0 + (size_t)b * KP);   // raw h after step 47
    float s = 0.f;
    #pragma unroll
    for (int j = 0; j < 16; j++) {
        uint32_t hu = hp[j * 32 + lane];
        float2 hf = __bfloat1622float2(*reinterpret_cast<const __nv_bfloat162*>(&hu));
        float2 wf = *(const float2*)(out_W + (j * 32 + lane) * 2);
        s = fmaf(hf.x, wf.x, s);
        s = fmaf(hf.y, wf.y, s);
    }
    #pragma unroll
    for (int o = 16; o > 0; o >>= 1) s += __shfl_down_sync(0xffffffffu, s, o);
    if (lane == 0) {
        float y = s + out_b[0];
        pred[b] = 1.f / (1.f + expf(-y));
        float lab = labels[b], tr = is_train[b];
        float mv = fmaxf(-y, 0.f);
        float bce = y - y * lab + mv + logf(expf(-mv) + expf(-y - mv));
        atomicAdd(&g_ynum, bce * tr);
        atomicAdd(&g_yden, tr);
    }
}

__global__ void fin_kernel(float* __restrict__ out) {
    __shared__ float sh[T];
    if (threadIdx.x < T)
        sh[threadIdx.x] = g_num[threadIdx.x] / (g_msum[threadIdx.x] + 1e-5f);
    __syncthreads();
    if (threadIdx.x == 0) {
        float s = 0.f;
        for (int t = 0; t < T; t++) s += sh[t];
        out[0] = 0.3f * s + g_ynum / (g_yden + 1e-5f);
    }
}

// ---------------- launch ----------------
extern "C" void kernel_launch(void* const* d_in, const int* in_sizes, int n_in,
                              void* d_out, int out_size) {
    const float* values   = (const float*)d_in[0];
    const float* masks    = (const float*)d_in[1];
    const float* deltas   = (const float*)d_in[2];
    const float* labels   = (const float*)d_in[3];
    const float* is_train = (const float*)d_in[4];
    const float* td_W     = (const float*)d_in[5];
    const float* td_b     = (const float*)d_in[6];
    const float* W_ih     = (const float*)d_in[7];
    const float* W_hh     = (const float*)d_in[8];
    const float* b_ih     = (const float*)d_in[9];
    const float* b_hh     = (const float*)d_in[10];
    const float* reg_W    = (const float*)d_in[11];
    const float* reg_b    = (const float*)d_in[12];
    const float* out_W    = (const float*)d_in[13];
    const float* out_b    = (const float*)d_in[14];

    float* out  = (float*)d_out;
    float* pred = out + 1;
    float* imp  = out + 1 + B;

    cudaFuncSetAttribute(step_kernel, cudaFuncAttributeMaxDynamicSharedMemorySize, 66560);

    zero_state_a<<<2048, 256>>>();
    zero_state_b<<<2048, 256>>>();
    pack_w_kernel<<<4096, 256>>>(W_hh, W_ih);
    pack_misc_kernel<<<412, 256>>>(td_W, b_ih, b_hh, reg_W);

    for (int t = 0; t < T; t++) {
        step_kernel<<<1056, 256, 66560>>>(values, masks, reg_b, imp, deltas, td_b, t, t & 1);
    }

    y_kernel<<<512, 256>>>(labels, is_train, out_W, out_b, pred);
    fin_kernel<<<1, 64>>>(out);
}